// round 14
// baseline (speedup 1.0000x reference)
#include <cuda_runtime.h>
#include <cuda_fp16.h>
#include <math.h>
#include <stdint.h>

#define WARP_FULL 0xFFFFFFFFu

// ---------------- scratch (device globals; no allocation) ----------------
__device__ __half g_wn0f[3][2048 * 64];     // [f][n][k] fp16 layer0 weights
__device__ __half g_wn1f[3][2048 * 2048];   // [f][n][k] fp16 layer1 weights
__device__ __half g_wn2f[3][64 * 2048];     // [f][n][k] fp16 layer2 weights
__device__ float  g_eg0 [3][2048];
__device__ float  g_eg1 [3][64 * 32 * 32];
__device__ float  g_eg2 [3][64 * 32];
__device__ __half g_xf [1024 * 64];         // fp16 flow input (GEMM path)
__device__ float  g_t1 [1024 * 2048];       // fp32 t1 (jac path)
__device__ __half g_t1f[1024 * 2048];       // fp16 t1 (GEMM path)
__device__ float  g_t2 [1024 * 2048];       // fp32 t2 (jac path)
__device__ __half g_t2f[1024 * 2048];       // fp16 t2 (GEMM path)
__device__ float  g_part[32 * 4 * 8 * 8192];  // K-split partials
__device__ float  g_h2 [1024 * 64];
__device__ float  g_xA [1024 * 64];
__device__ float  g_xB [1024 * 64];
__device__ float  g_lterm[1024 * 64];

struct PrepPtrs { const float* W[9]; const float* dw[9]; const float* x; };

__device__ __forceinline__ void mma16816(float* c, const uint32_t* a, const uint32_t* b) {
    asm volatile("mma.sync.aligned.m16n8k16.row.col.f32.f16.f16.f32 "
        "{%0,%1,%2,%3}, {%4,%5,%6,%7}, {%8,%9}, {%0,%1,%2,%3};"
        : "+f"(c[0]), "+f"(c[1]), "+f"(c[2]), "+f"(c[3])
        : "r"(a[0]), "r"(a[1]), "r"(a[2]), "r"(a[3]), "r"(b[0]), "r"(b[1]));
}
__device__ __forceinline__ uint32_t smem_u32(const void* p) {
    uint32_t a;
    asm("{ .reg .u64 t; cvta.to.shared.u64 t, %1; cvt.u32.u64 %0, t; }" : "=r"(a) : "l"(p));
    return a;
}
__device__ __forceinline__ void cp16(uint32_t dst, const void* src) {
    asm volatile("cp.async.cg.shared.global [%0], [%1], 16;" :: "r"(dst), "l"(src));
}
#define CP_COMMIT() asm volatile("cp.async.commit_group;" ::: "memory")
#define CP_WAIT(n)  asm volatile("cp.async.wait_group %0;" :: "n"(n) : "memory")

// ---------------- merged weight preprocessing + x conversion ----------------
// grid (521, 3): wr<2048 layer0 rows, <4096 layer1, <4160 layer2, else xconv (f==0).
__global__ void __launch_bounds__(256) prep_all_kernel(PrepPtrs P) {
    int f = blockIdx.y;
    int wr = blockIdx.x * 8 + (threadIdx.x >> 5);
    int lane = threadIdx.x & 31;

    if (wr < 2048) {                        // ---- layer0 (fp16 [n][k])
        const float* W  = P.W [f * 3 + 0];
        const float* dw = P.dw[f * 3 + 0];
        int r = wr, blk = r >> 5;
        float vals[2]; float s = 0.f;
        #pragma unroll
        for (int i = 0; i < 2; i++) {
            int c = lane + 32 * i;
            float raw = W[r * 64 + c];
            float v = (c < blk) ? raw : ((c == blk) ? expf(raw) : 0.f);
            vals[i] = v; s += v * v;
        }
        #pragma unroll
        for (int off = 16; off; off >>= 1) s += __shfl_xor_sync(WARP_FULL, s, off);
        float scale = expf(dw[r]) * rsqrtf(s);
        #pragma unroll
        for (int i = 0; i < 2; i++) {
            int c = lane + 32 * i;
            float wv = vals[i] * scale;
            g_wn0f[f][r * 64 + c] = __float2half(wv);
            if (c == blk) g_eg0[f][r] = wv;
        }
    } else if (wr < 4096) {                 // ---- layer1 (fp16)
        const float* W  = P.W [f * 3 + 1];
        const float* dw = P.dw[f * 3 + 1];
        int r = wr - 2048, blk = r >> 5;
        int d0 = blk * 32, d1 = d0 + 32;
        int cmax = ((r >> 6) + 1) << 6;
        float s = 0.f;
        for (int c = lane; c < d1; c += 32) {
            float wv = W[r * 2048 + c];
            if (c >= d0) wv = expf(wv);
            s += wv * wv;
        }
        #pragma unroll
        for (int off = 16; off; off >>= 1) s += __shfl_xor_sync(WARP_FULL, s, off);
        float scale = expf(dw[r]) * rsqrtf(s);
        for (int c = lane; c < cmax; c += 32) {
            float o;
            if (c < d0)       o = W[r * 2048 + c] * scale;
            else if (c < d1) {
                o = expf(W[r * 2048 + c]) * scale;
                g_eg1[f][blk * 1024 + (c - d0) * 32 + (r & 31)] = o;
            } else            o = 0.f;
            g_wn1f[f][r * 2048 + c] = __float2half(o);
        }
    } else if (wr < 4160) {                 // ---- layer2 (fp16 [n][k])
        const float* W  = P.W [f * 3 + 2];
        const float* dw = P.dw[f * 3 + 2];
        int r = wr - 4096;
        int d0 = r * 32, d1 = d0 + 32;
        float s = 0.f;
        for (int c = lane; c < d1; c += 32) {
            float wv = W[r * 2048 + c];
            if (c >= d0) wv = expf(wv);
            s += wv * wv;
        }
        #pragma unroll
        for (int off = 16; off; off >>= 1) s += __shfl_xor_sync(WARP_FULL, s, off);
        float scale = expf(dw[r]) * rsqrtf(s);
        for (int c = lane; c < 2048; c += 32) {
            float o;
            if (c < d0)       o = W[r * 2048 + c] * scale;
            else if (c < d1) {
                o = expf(W[r * 2048 + c]) * scale;
                g_eg2[f][r * 32 + (c - d0)] = o;
            } else            o = 0.f;
            g_wn2f[f][r * 2048 + c] = __float2half(o);
        }
    } else if (f == 0) {                    // ---- x conversion (8 warps cover 64K elems / 8)
        int base = (wr - 4160) * 8192;      // wr 4160..4167 -> 8 warps, 8192 each
        for (int i = lane; i < 8192; i += 32)
            g_xf[base + i] = __float2half(P.x[base + i]);
    }
}

// ---------------- shared HMMA core: 2-stage cp.async double buffer ----------------
#define L1_A 0
#define L1_B (128 * 40)
#define L1_BUF (192 * 40)                 // 7680 halves / buffer
#define L1_SMEM_BYTES (2 * L1_BUF * 2)    // 30720 bytes

__device__ __forceinline__ void hmma_core(const __half* __restrict__ Aglob, int m0, int astr,
                                          const __half* __restrict__ Bglob, int n0, int bstr,
                                          int kbeg, int kend, __half* smh,
                                          float acc[2][4][4]) {
    const uint32_t sb = smem_u32(smh);
    const int tid = threadIdx.x;
    const int w = tid >> 5, l = tid & 31;
    const int mw = (w & 3) * 32, nw = (w >> 2) * 32;
    const int lr = l >> 2, lc2 = (l & 3) * 2;
    const int ra = tid >> 2, qa = (tid & 3) * 8;

    auto load_chunk = [&](uint32_t base, int kc) {
        cp16(base + (uint32_t)(L1_A + ra * 40 + qa) * 2,        &Aglob[(m0 + ra) * astr + kc + qa]);
        cp16(base + (uint32_t)(L1_A + (ra + 64) * 40 + qa) * 2, &Aglob[(m0 + ra + 64) * astr + kc + qa]);
        cp16(base + (uint32_t)(L1_B + ra * 40 + qa) * 2,        &Bglob[(n0 + ra) * bstr + kc + qa]);
        CP_COMMIT();
    };

    load_chunk(sb, kbeg);
    int buf = 0;
    for (int kc = kbeg; kc < kend; kc += 32) {
        bool more = (kc + 32) < kend;
        if (more) load_chunk(sb + (uint32_t)(buf ^ 1) * L1_BUF * 2, kc + 32);
        if (more) { CP_WAIT(1); } else { CP_WAIT(0); }
        __syncthreads();

        const __half* S = smh + buf * L1_BUF;
        #pragma unroll
        for (int kk = 0; kk < 32; kk += 16) {
            uint32_t a[2][4], b[4][2];
            #pragma unroll
            for (int i = 0; i < 2; i++) {
                int R = mw + i * 16 + lr;
                a[i][0] = *(const uint32_t*)&S[L1_A + R * 40 + kk + lc2];
                a[i][1] = *(const uint32_t*)&S[L1_A + (R + 8) * 40 + kk + lc2];
                a[i][2] = *(const uint32_t*)&S[L1_A + R * 40 + kk + 8 + lc2];
                a[i][3] = *(const uint32_t*)&S[L1_A + (R + 8) * 40 + kk + 8 + lc2];
            }
            #pragma unroll
            for (int j = 0; j < 4; j++) {
                int N = nw + j * 8 + lr;
                b[j][0] = *(const uint32_t*)&S[L1_B + N * 40 + kk + lc2];
                b[j][1] = *(const uint32_t*)&S[L1_B + N * 40 + kk + 8 + lc2];
            }
            #pragma unroll
            for (int i = 0; i < 2; i++)
                #pragma unroll
                for (int j = 0; j < 4; j++)
                    mma16816(acc[i][j], a[i], b[j]);
        }
        __syncthreads();
        buf ^= 1;
    }
}

// ---------------- layer 0: t1 = tanh(xf @ wn0^T + b0), fused HMMA epilogue ----------------
__global__ void __launch_bounds__(256) layer0h_kernel(int f, const float* __restrict__ bias) {
    extern __shared__ __half smh[];
    const int nt = blockIdx.x, mt = blockIdx.y;
    const int m0 = mt * 128, n0 = nt * 64;
    float acc[2][4][4] = {};
    hmma_core(g_xf, m0, 64, g_wn0f[f], n0, 64, 0, 64, smh, acc);

    const int tid = threadIdx.x;
    const int w = tid >> 5, l = tid & 31;
    const int mw = (w & 3) * 32, nw = (w >> 2) * 32;
    const int lr = l >> 2, lc2 = (l & 3) * 2;
    #pragma unroll
    for (int i = 0; i < 2; i++) {
        int r = m0 + mw + i * 16 + lr;
        #pragma unroll
        for (int j = 0; j < 4; j++) {
            int n = n0 + nw + j * 8 + lc2;
            float b0 = bias[n], b1 = bias[n + 1];
            float t0a = tanhf(acc[i][j][0] + b0);
            float t1a = tanhf(acc[i][j][1] + b1);
            float t0b = tanhf(acc[i][j][2] + b0);
            float t1b = tanhf(acc[i][j][3] + b1);
            *reinterpret_cast<float2*>(&g_t1[r * 2048 + n])       = make_float2(t0a, t1a);
            *reinterpret_cast<float2*>(&g_t1[(r + 8) * 2048 + n]) = make_float2(t0b, t1b);
            *reinterpret_cast<__half2*>(&g_t1f[r * 2048 + n])       = __floats2half2_rn(t0a, t1a);
            *reinterpret_cast<__half2*>(&g_t1f[(r + 8) * 2048 + n]) = __floats2half2_rn(t0b, t1b);
        }
    }
}

// ---------------- partial-writing epilogue (layers 1,2) ----------------
__device__ __forceinline__ void write_partials(float acc[2][4][4], float* __restrict__ out) {
    const int tid = threadIdx.x;
    const int w = tid >> 5, l = tid & 31;
    const int mw = (w & 3) * 32, nw = (w >> 2) * 32;
    const int lr = l >> 2, lc2 = (l & 3) * 2;
    #pragma unroll
    for (int i = 0; i < 2; i++) {
        int r = mw + i * 16 + lr;
        #pragma unroll
        for (int j = 0; j < 4; j++) {
            int n = nw + j * 8 + lc2;
            *reinterpret_cast<float2*>(&out[r * 64 + n])       = make_float2(acc[i][j][0], acc[i][j][1]);
            *reinterpret_cast<float2*>(&out[(r + 8) * 64 + n]) = make_float2(acc[i][j][2], acc[i][j][3]);
        }
    }
}

// ---------------- layer 1: fp16 HMMA, triangular K-split ----------------
__global__ void __launch_bounds__(256) layer1_mma_kernel(int f) {
    const int nt = blockIdx.x, mt = blockIdx.y, ch = blockIdx.z;
    const int Klim = (nt + 1) * 64;
    const int kbeg = ch * 512;
    if (kbeg >= Klim) return;
    const int kend = min(kbeg + 512, Klim);
    extern __shared__ __half smh[];
    float acc[2][4][4] = {};
    hmma_core(g_t1f, mt * 128, 2048, g_wn1f[f], nt * 64, 2048, kbeg, kend, smh, acc);
    write_partials(acc, &g_part[(size_t)((nt * 4 + ch) * 8 + mt) * 8192]);
}

// ---------------- layer1 reduce: t2 = tanh(sum partials + b1), fp32 + fp16 ----------------
__global__ void __launch_bounds__(256) reduce1_kernel(const float* __restrict__ bias) {
    const int nt = blockIdx.x, ms = blockIdx.y;
    const int mt = ms >> 2, sub = ms & 3;
    const int Cnt = (nt + 8) >> 3;
    const int n0 = nt * 64;
    const float* base = &g_part[(size_t)((nt * 4) * 8 + mt) * 8192 + sub * 2048];
    const int row0 = mt * 128 + sub * 32;
    for (int e = threadIdx.x * 4; e < 2048; e += 1024) {
        float4 s = *reinterpret_cast<const float4*>(&base[e]);
        for (int c = 1; c < Cnt; c++) {
            float4 p = *reinterpret_cast<const float4*>(&base[(size_t)c * 65536 + e]);
            s.x += p.x; s.y += p.y; s.z += p.z; s.w += p.w;
        }
        int m = e >> 6, n = e & 63;
        float4 bv = *reinterpret_cast<const float4*>(&bias[n0 + n]);
        float4 o;
        o.x = tanhf(s.x + bv.x); o.y = tanhf(s.y + bv.y);
        o.z = tanhf(s.z + bv.z); o.w = tanhf(s.w + bv.w);
        int idx = (row0 + m) * 2048 + n0 + n;
        *reinterpret_cast<float4*>(&g_t2[idx]) = o;
        *reinterpret_cast<__half2*>(&g_t2f[idx])     = __floats2half2_rn(o.x, o.y);
        *reinterpret_cast<__half2*>(&g_t2f[idx + 2]) = __floats2half2_rn(o.z, o.w);
    }
}

// ---------------- layer 2: fp16 HMMA, K-split 16 x 128 ----------------
__global__ void __launch_bounds__(256) layer2_mma_kernel(int f) {
    const int mt = blockIdx.x, ch = blockIdx.y;
    extern __shared__ __half smh[];
    float acc[2][4][4] = {};
    hmma_core(g_t2f, mt * 128, 2048, g_wn2f[f], 0, 2048, ch * 128, ch * 128 + 128, smh, acc);
    write_partials(acc, &g_part[(size_t)(ch * 8 + mt) * 8192]);
}

// ---------------- layer2 reduce: h2 = sum partials ----------------
__global__ void __launch_bounds__(256) reduce2_kernel() {
    int gidx = blockIdx.x * 1024 + threadIdx.x * 4;     // 0..65535
    float4 s = *reinterpret_cast<const float4*>(&g_part[gidx]);
    #pragma unroll
    for (int c = 1; c < 16; c++) {
        float4 p = *reinterpret_cast<const float4*>(&g_part[(size_t)c * 65536 + gidx]);
        s.x += p.x; s.y += p.y; s.z += p.z; s.w += p.w;
    }
    int m = (gidx >> 13) * 128 + ((gidx & 8191) >> 6);
    int n = gidx & 63;
    *reinterpret_cast<float4*>(&g_h2[m * 64 + n]) = s;
}

// ---------------- Jacobian chain + gate + flip (4-way split accumulators) ----------------
__global__ void __launch_bounds__(256) jac_kernel(const float* __restrict__ xext,
                                                  int xsel, int nsel, int f,
                                                  const float* __restrict__ gate,
                                                  int hasGate, int accum,
                                                  const float* __restrict__ b2) {
    __shared__ float eg1s[1024];
    __shared__ float eg0s[32];
    __shared__ float eg2s[32];
    int d = blockIdx.x;
    int lane = threadIdx.x & 31, w = threadIdx.x >> 5;
    for (int i = threadIdx.x; i < 1024; i += 256) eg1s[i] = g_eg1[f][d * 1024 + i];
    if (threadIdx.x < 32) {
        eg0s[threadIdx.x] = g_eg0[f][d * 32 + threadIdx.x];
        eg2s[threadIdx.x] = g_eg2[f][d * 32 + threadIdx.x];
    }
    __syncthreads();
    const float* xcur = (xsel == 0) ? xext : ((xsel == 1) ? (const float*)g_xA : (const float*)g_xB);
    float* xnext = (nsel == 1) ? g_xA : g_xB;
    float gt = 0.f;
    if (hasGate) gt = *gate;
    float bias_d = b2[d];

    for (int bi = 0; bi < 16; bi++) {
        int b = blockIdx.y * 128 + bi * 8 + w;
        int idx = b * 2048 + d * 32 + lane;
        float t1v = g_t1[idx];
        float v0 = eg0s[lane] * (1.f - t1v * t1v);
        // 4 independent FMA chains (break serial accumulator dependency)
        float a0 = 0.f, a1 = 0.f, a2 = 0.f, a3 = 0.f;
        #pragma unroll
        for (int k = 0; k < 32; k += 4) {
            a0 = fmaf(eg1s[(k + 0) * 32 + lane], __shfl_sync(WARP_FULL, v0, k + 0), a0);
            a1 = fmaf(eg1s[(k + 1) * 32 + lane], __shfl_sync(WARP_FULL, v0, k + 1), a1);
            a2 = fmaf(eg1s[(k + 2) * 32 + lane], __shfl_sync(WARP_FULL, v0, k + 2), a2);
            a3 = fmaf(eg1s[(k + 3) * 32 + lane], __shfl_sync(WARP_FULL, v0, k + 3), a3);
        }
        float acc = (a0 + a1) + (a2 + a3);
        float t2v = g_t2[idx];
        float term = eg2s[lane] * acc * (1.f - t2v * t2v);
        #pragma unroll
        for (int off = 16; off; off >>= 1) term += __shfl_xor_sync(WARP_FULL, term, off);

        if (lane == 0) {
            float g = logf(term);
            float outv = g_h2[b * 64 + d] + bias_d;
            float l;
            if (hasGate) {
                float z = g + gt;
                float sp1 = (z  > 20.f) ? z  : log1pf(expf(z));
                float sp0 = (gt > 20.f) ? gt : log1pf(expf(gt));
                l = sp1 - sp0;
                float sgm = 1.f / (1.f + expf(-gt));
                float xo = sgm * outv + (1.f - sgm) * xcur[b * 64 + d];
                xnext[b * 64 + (63 - d)] = xo;
                g_xf[b * 64 + (63 - d)] = __float2half(xo);
            } else {
                l = g;
                xnext[b * 64 + d] = outv;
            }
            if (accum) g_lterm[b * 64 + d] += l;
            else       g_lterm[b * 64 + d]  = l;
        }
    }
}

// ---------------- final reduction ----------------
__global__ void __launch_bounds__(256) final_kernel(int xsel, float* __restrict__ out) {
    const float* xf = (xsel == 1) ? (const float*)g_xA : (const float*)g_xB;
    int b = blockIdx.x * 8 + (threadIdx.x >> 5);
    int lane = threadIdx.x & 31;
    float v1 = xf[b * 64 + lane];
    float v2 = xf[b * 64 + 32 + lane];
    float s = -0.5f * (v1 * v1 + v2 * v2)
              + g_lterm[b * 64 + lane] + g_lterm[b * 64 + 32 + lane];
    #pragma unroll
    for (int off = 16; off; off >>= 1) s += __shfl_xor_sync(WARP_FULL, s, off);
    if (lane == 0) out[b] = s - 32.f * 1.8378770664093453f;
}

// ---------------- launch ----------------
extern "C" void kernel_launch(void* const* d_in, const int* in_sizes, int n_in,
                              void* d_out, int out_size) {
    (void)in_sizes; (void)n_in; (void)out_size;
    const float* x     = (const float*)d_in[0];
    const float* gate0 = (const float*)d_in[28];
    const float* gate1 = (const float*)d_in[29];

    PrepPtrs P;
    for (int f = 0; f < 3; f++)
        for (int l = 0; l < 3; l++) {
            P.W [f * 3 + l] = (const float*)d_in[1 + f * 9 + l * 3 + 0];
            P.dw[f * 3 + l] = (const float*)d_in[1 + f * 9 + l * 3 + 1];
        }
    P.x = x;
    prep_all_kernel<<<dim3(521, 3), 256>>>(P);

    int xsel = 0;
    for (int f = 0; f < 3; f++) {
        const float* b0 = (const float*)d_in[1 + f * 9 + 2];
        const float* b1 = (const float*)d_in[1 + f * 9 + 5];
        const float* b2 = (const float*)d_in[1 + f * 9 + 8];

        layer0h_kernel<<<dim3(32, 8), 256, L1_SMEM_BYTES>>>(f, b0);
        layer1_mma_kernel<<<dim3(32, 8, 4), 256, L1_SMEM_BYTES>>>(f);
        reduce1_kernel<<<dim3(32, 32), 256>>>(b1);
        layer2_mma_kernel<<<dim3(8, 16), 256, L1_SMEM_BYTES>>>(f);
        reduce2_kernel<<<64, 256>>>();

        const float* gate = (f == 0) ? gate0 : ((f == 1) ? gate1 : nullptr);
        int nsel = (f & 1) ? 2 : 1;
        jac_kernel<<<dim3(64, 8), 256>>>(x, xsel, nsel, f, gate, (f < 2) ? 1 : 0, (f > 0) ? 1 : 0, b2);
        xsel = nsel;
    }
    final_kernel<<<128, 256>>>(xsel, (float*)d_out);
}

// round 15
// speedup vs baseline: 1.1637x; 1.1637x over previous
#include <cuda_runtime.h>
#include <cuda_fp16.h>
#include <math.h>
#include <stdint.h>

#define WARP_FULL 0xFFFFFFFFu

// ---------------- scratch (device globals; no allocation) ----------------
__device__ __half g_wn0f[3][2048 * 64];     // [f][n][k] fp16 layer0 weights
__device__ __half g_wn1f[3][2048 * 2048];   // [f][n][k] fp16 layer1 weights
__device__ __half g_wn2f[3][64 * 2048];     // [f][n][k] fp16 layer2 weights
__device__ float  g_eg0 [3][2048];
__device__ float  g_eg1 [3][64 * 32 * 32];
__device__ float  g_eg2 [3][64 * 32];
__device__ __half g_xf [1024 * 64];         // fp16 flow input (GEMM path)
__device__ float  g_t1 [1024 * 2048];       // fp32 t1 (jac path)
__device__ __half g_t1f[1024 * 2048];       // fp16 t1 (GEMM path)
__device__ float  g_t2 [1024 * 2048];       // fp32 t2 (jac path)
__device__ __half g_t2f[1024 * 2048];       // fp16 t2 (GEMM path)
__device__ float  g_part[32 * 8 * 8 * 8192];  // K-split partials (8 chunks of 256)
__device__ float  g_h2 [1024 * 64];
__device__ float  g_xA [1024 * 64];
__device__ float  g_xB [1024 * 64];
__device__ float  g_lterm[1024 * 64];

struct PrepPtrs { const float* W[9]; const float* dw[9]; };

__device__ __forceinline__ void mma16816(float* c, const uint32_t* a, const uint32_t* b) {
    asm volatile("mma.sync.aligned.m16n8k16.row.col.f32.f16.f16.f32 "
        "{%0,%1,%2,%3}, {%4,%5,%6,%7}, {%8,%9}, {%0,%1,%2,%3};"
        : "+f"(c[0]), "+f"(c[1]), "+f"(c[2]), "+f"(c[3])
        : "r"(a[0]), "r"(a[1]), "r"(a[2]), "r"(a[3]), "r"(b[0]), "r"(b[1]));
}
__device__ __forceinline__ uint32_t smem_u32(const void* p) {
    uint32_t a;
    asm("{ .reg .u64 t; cvta.to.shared.u64 t, %1; cvt.u32.u64 %0, t; }" : "=r"(a) : "l"(p));
    return a;
}
__device__ __forceinline__ void cp16(uint32_t dst, const void* src) {
    asm volatile("cp.async.cg.shared.global [%0], [%1], 16;" :: "r"(dst), "l"(src));
}
#define CP_COMMIT() asm volatile("cp.async.commit_group;" ::: "memory")
#define CP_WAIT(n)  asm volatile("cp.async.wait_group %0;" :: "n"(n) : "memory")

// ---------------- merged weight preprocessing: warp per row ----------------
__global__ void __launch_bounds__(256) prep_all_kernel(PrepPtrs P) {
    int f = blockIdx.y;
    int wr = blockIdx.x * 8 + (threadIdx.x >> 5);
    int lane = threadIdx.x & 31;

    if (wr < 2048) {                        // ---- layer0 (fp16 [n][k])
        const float* W  = P.W [f * 3 + 0];
        const float* dw = P.dw[f * 3 + 0];
        int r = wr, blk = r >> 5;
        float vals[2]; float s = 0.f;
        #pragma unroll
        for (int i = 0; i < 2; i++) {
            int c = lane + 32 * i;
            float raw = W[r * 64 + c];
            float v = (c < blk) ? raw : ((c == blk) ? expf(raw) : 0.f);
            vals[i] = v; s += v * v;
        }
        #pragma unroll
        for (int off = 16; off; off >>= 1) s += __shfl_xor_sync(WARP_FULL, s, off);
        float scale = expf(dw[r]) * rsqrtf(s);
        #pragma unroll
        for (int i = 0; i < 2; i++) {
            int c = lane + 32 * i;
            float wv = vals[i] * scale;
            g_wn0f[f][r * 64 + c] = __float2half(wv);
            if (c == blk) g_eg0[f][r] = wv;
        }
    } else if (wr < 4096) {                 // ---- layer1 (fp16)
        const float* W  = P.W [f * 3 + 1];
        const float* dw = P.dw[f * 3 + 1];
        int r = wr - 2048, blk = r >> 5;
        int d0 = blk * 32, d1 = d0 + 32;
        int cmax = ((r >> 6) + 1) << 6;
        float s = 0.f;
        for (int c = lane; c < d1; c += 32) {
            float wv = W[r * 2048 + c];
            if (c >= d0) wv = expf(wv);
            s += wv * wv;
        }
        #pragma unroll
        for (int off = 16; off; off >>= 1) s += __shfl_xor_sync(WARP_FULL, s, off);
        float scale = expf(dw[r]) * rsqrtf(s);
        for (int c = lane; c < cmax; c += 32) {
            float o;
            if (c < d0)       o = W[r * 2048 + c] * scale;
            else if (c < d1) {
                o = expf(W[r * 2048 + c]) * scale;
                g_eg1[f][blk * 1024 + (c - d0) * 32 + (r & 31)] = o;
            } else            o = 0.f;
            g_wn1f[f][r * 2048 + c] = __float2half(o);
        }
    } else {                                // ---- layer2 (fp16 [n][k])
        const float* W  = P.W [f * 3 + 2];
        const float* dw = P.dw[f * 3 + 2];
        int r = wr - 4096;
        int d0 = r * 32, d1 = d0 + 32;
        float s = 0.f;
        for (int c = lane; c < d1; c += 32) {
            float wv = W[r * 2048 + c];
            if (c >= d0) wv = expf(wv);
            s += wv * wv;
        }
        #pragma unroll
        for (int off = 16; off; off >>= 1) s += __shfl_xor_sync(WARP_FULL, s, off);
        float scale = expf(dw[r]) * rsqrtf(s);
        for (int c = lane; c < 2048; c += 32) {
            float o;
            if (c < d0)       o = W[r * 2048 + c] * scale;
            else if (c < d1) {
                o = expf(W[r * 2048 + c]) * scale;
                g_eg2[f][r * 32 + (c - d0)] = o;
            } else            o = 0.f;
            g_wn2f[f][r * 2048 + c] = __float2half(o);
        }
    }
}

// ---------------- x conversion (flow 0 only) ----------------
__global__ void __launch_bounds__(256) xconv_kernel(const float* __restrict__ x) {
    int i = blockIdx.x * 256 + threadIdx.x;
    g_xf[i] = __float2half(x[i]);
}

// ---------------- shared HMMA core: 2-stage cp.async double buffer ----------------
#define L1_A 0
#define L1_B (128 * 40)
#define L1_BUF (192 * 40)                 // 7680 halves / buffer
#define L1_SMEM_BYTES (2 * L1_BUF * 2)    // 30720 bytes

__device__ __forceinline__ void hmma_core(const __half* __restrict__ Aglob, int m0, int astr,
                                          const __half* __restrict__ Bglob, int n0, int bstr,
                                          int kbeg, int kend, __half* smh,
                                          float acc[2][4][4]) {
    const uint32_t sb = smem_u32(smh);
    const int tid = threadIdx.x;
    const int w = tid >> 5, l = tid & 31;
    const int mw = (w & 3) * 32, nw = (w >> 2) * 32;
    const int lr = l >> 2, lc2 = (l & 3) * 2;
    const int ra = tid >> 2, qa = (tid & 3) * 8;

    auto load_chunk = [&](uint32_t base, int kc) {
        cp16(base + (uint32_t)(L1_A + ra * 40 + qa) * 2,        &Aglob[(m0 + ra) * astr + kc + qa]);
        cp16(base + (uint32_t)(L1_A + (ra + 64) * 40 + qa) * 2, &Aglob[(m0 + ra + 64) * astr + kc + qa]);
        cp16(base + (uint32_t)(L1_B + ra * 40 + qa) * 2,        &Bglob[(n0 + ra) * bstr + kc + qa]);
        CP_COMMIT();
    };

    load_chunk(sb, kbeg);
    int buf = 0;
    for (int kc = kbeg; kc < kend; kc += 32) {
        bool more = (kc + 32) < kend;
        if (more) load_chunk(sb + (uint32_t)(buf ^ 1) * L1_BUF * 2, kc + 32);
        if (more) { CP_WAIT(1); } else { CP_WAIT(0); }
        __syncthreads();

        const __half* S = smh + buf * L1_BUF;
        #pragma unroll
        for (int kk = 0; kk < 32; kk += 16) {
            uint32_t a[2][4], b[4][2];
            #pragma unroll
            for (int i = 0; i < 2; i++) {
                int R = mw + i * 16 + lr;
                a[i][0] = *(const uint32_t*)&S[L1_A + R * 40 + kk + lc2];
                a[i][1] = *(const uint32_t*)&S[L1_A + (R + 8) * 40 + kk + lc2];
                a[i][2] = *(const uint32_t*)&S[L1_A + R * 40 + kk + 8 + lc2];
                a[i][3] = *(const uint32_t*)&S[L1_A + (R + 8) * 40 + kk + 8 + lc2];
            }
            #pragma unroll
            for (int j = 0; j < 4; j++) {
                int N = nw + j * 8 + lr;
                b[j][0] = *(const uint32_t*)&S[L1_B + N * 40 + kk + lc2];
                b[j][1] = *(const uint32_t*)&S[L1_B + N * 40 + kk + 8 + lc2];
            }
            #pragma unroll
            for (int i = 0; i < 2; i++)
                #pragma unroll
                for (int j = 0; j < 4; j++)
                    mma16816(acc[i][j], a[i], b[j]);
        }
        __syncthreads();
        buf ^= 1;
    }
}

// ---------------- layer 0: t1 = tanh(xf @ wn0^T + b0), fused HMMA epilogue ----------------
__global__ void __launch_bounds__(256) layer0h_kernel(int f, const float* __restrict__ bias) {
    extern __shared__ __half smh[];
    const int nt = blockIdx.x, mt = blockIdx.y;
    const int m0 = mt * 128, n0 = nt * 64;
    float acc[2][4][4] = {};
    hmma_core(g_xf, m0, 64, g_wn0f[f], n0, 64, 0, 64, smh, acc);

    const int tid = threadIdx.x;
    const int w = tid >> 5, l = tid & 31;
    const int mw = (w & 3) * 32, nw = (w >> 2) * 32;
    const int lr = l >> 2, lc2 = (l & 3) * 2;
    #pragma unroll
    for (int i = 0; i < 2; i++) {
        int r = m0 + mw + i * 16 + lr;
        #pragma unroll
        for (int j = 0; j < 4; j++) {
            int n = n0 + nw + j * 8 + lc2;
            float b0 = bias[n], b1 = bias[n + 1];
            float t0a = tanhf(acc[i][j][0] + b0);
            float t1a = tanhf(acc[i][j][1] + b1);
            float t0b = tanhf(acc[i][j][2] + b0);
            float t1b = tanhf(acc[i][j][3] + b1);
            *reinterpret_cast<float2*>(&g_t1[r * 2048 + n])       = make_float2(t0a, t1a);
            *reinterpret_cast<float2*>(&g_t1[(r + 8) * 2048 + n]) = make_float2(t0b, t1b);
            *reinterpret_cast<__half2*>(&g_t1f[r * 2048 + n])       = __floats2half2_rn(t0a, t1a);
            *reinterpret_cast<__half2*>(&g_t1f[(r + 8) * 2048 + n]) = __floats2half2_rn(t0b, t1b);
        }
    }
}

// ---------------- partial-writing epilogue (layers 1,2) ----------------
__device__ __forceinline__ void write_partials(float acc[2][4][4], float* __restrict__ out) {
    const int tid = threadIdx.x;
    const int w = tid >> 5, l = tid & 31;
    const int mw = (w & 3) * 32, nw = (w >> 2) * 32;
    const int lr = l >> 2, lc2 = (l & 3) * 2;
    #pragma unroll
    for (int i = 0; i < 2; i++) {
        int r = mw + i * 16 + lr;
        #pragma unroll
        for (int j = 0; j < 4; j++) {
            int n = nw + j * 8 + lc2;
            *reinterpret_cast<float2*>(&out[r * 64 + n])       = make_float2(acc[i][j][0], acc[i][j][1]);
            *reinterpret_cast<float2*>(&out[(r + 8) * 64 + n]) = make_float2(acc[i][j][2], acc[i][j][3]);
        }
    }
}

// ---------------- layer 1: fp16 HMMA, triangular K-split (256-wide chunks) ----------------
__global__ void __launch_bounds__(256) layer1_mma_kernel(int f) {
    const int nt = blockIdx.x, mt = blockIdx.y, ch = blockIdx.z;
    const int Klim = (nt + 1) * 64;
    const int kbeg = ch * 256;
    if (kbeg >= Klim) return;
    const int kend = min(kbeg + 256, Klim);
    extern __shared__ __half smh[];
    float acc[2][4][4] = {};
    hmma_core(g_t1f, mt * 128, 2048, g_wn1f[f], nt * 64, 2048, kbeg, kend, smh, acc);
    write_partials(acc, &g_part[(size_t)((nt * 8 + ch) * 8 + mt) * 8192]);
}

// ---------------- layer1 reduce: t2 = tanh(sum partials + b1), fp32 + fp16 ----------------
__global__ void __launch_bounds__(256) reduce1_kernel(const float* __restrict__ bias) {
    const int nt = blockIdx.x, ms = blockIdx.y;
    const int mt = ms >> 2, sub = ms & 3;
    const int Cnt = (nt + 4) >> 2;        // ceil((nt+1)*64 / 256)
    const int n0 = nt * 64;
    const float* base = &g_part[(size_t)((nt * 8) * 8 + mt) * 8192 + sub * 2048];
    const int row0 = mt * 128 + sub * 32;
    for (int e = threadIdx.x * 4; e < 2048; e += 1024) {
        float4 s = *reinterpret_cast<const float4*>(&base[e]);
        for (int c = 1; c < Cnt; c++) {
            float4 p = *reinterpret_cast<const float4*>(&base[(size_t)c * 65536 + e]);
            s.x += p.x; s.y += p.y; s.z += p.z; s.w += p.w;
        }
        int m = e >> 6, n = e & 63;
        float4 bv = *reinterpret_cast<const float4*>(&bias[n0 + n]);
        float4 o;
        o.x = tanhf(s.x + bv.x); o.y = tanhf(s.y + bv.y);
        o.z = tanhf(s.z + bv.z); o.w = tanhf(s.w + bv.w);
        int idx = (row0 + m) * 2048 + n0 + n;
        *reinterpret_cast<float4*>(&g_t2[idx]) = o;
        *reinterpret_cast<__half2*>(&g_t2f[idx])     = __floats2half2_rn(o.x, o.y);
        *reinterpret_cast<__half2*>(&g_t2f[idx + 2]) = __floats2half2_rn(o.z, o.w);
    }
}

// ---------------- layer 2: fp16 HMMA, K-split 16 x 128 ----------------
__global__ void __launch_bounds__(256) layer2_mma_kernel(int f) {
    const int mt = blockIdx.x, ch = blockIdx.y;
    extern __shared__ __half smh[];
    float acc[2][4][4] = {};
    hmma_core(g_t2f, mt * 128, 2048, g_wn2f[f], 0, 2048, ch * 128, ch * 128 + 128, smh, acc);
    write_partials(acc, &g_part[(size_t)(ch * 8 + mt) * 8192]);
}

// ---------------- layer2 reduce: h2 = sum partials ----------------
__global__ void __launch_bounds__(256) reduce2_kernel() {
    int gidx = blockIdx.x * 1024 + threadIdx.x * 4;     // 0..65535
    float4 s = *reinterpret_cast<const float4*>(&g_part[gidx]);
    #pragma unroll
    for (int c = 1; c < 16; c++) {
        float4 p = *reinterpret_cast<const float4*>(&g_part[(size_t)c * 65536 + gidx]);
        s.x += p.x; s.y += p.y; s.z += p.z; s.w += p.w;
    }
    int m = (gidx >> 13) * 128 + ((gidx & 8191) >> 6);
    int n = gidx & 63;
    *reinterpret_cast<float4*>(&g_h2[m * 64 + n]) = s;
}

// ---------------- Jacobian chain + gate + flip (serial chain — proven) ----------------
__global__ void __launch_bounds__(256) jac_kernel(const float* __restrict__ xext,
                                                  int xsel, int nsel, int f,
                                                  const float* __restrict__ gate,
                                                  int hasGate, int accum,
                                                  const float* __restrict__ b2) {
    __shared__ float eg1s[1024];
    __shared__ float eg0s[32];
    __shared__ float eg2s[32];
    int d = blockIdx.x;
    int lane = threadIdx.x & 31, w = threadIdx.x >> 5;
    for (int i = threadIdx.x; i < 1024; i += 256) eg1s[i] = g_eg1[f][d * 1024 + i];
    if (threadIdx.x < 32) {
        eg0s[threadIdx.x] = g_eg0[f][d * 32 + threadIdx.x];
        eg2s[threadIdx.x] = g_eg2[f][d * 32 + threadIdx.x];
    }
    __syncthreads();
    const float* xcur = (xsel == 0) ? xext : ((xsel == 1) ? (const float*)g_xA : (const float*)g_xB);
    float* xnext = (nsel == 1) ? g_xA : g_xB;
    float gt = 0.f;
    if (hasGate) gt = *gate;
    float bias_d = b2[d];

    for (int bi = 0; bi < 16; bi++) {
        int b = blockIdx.y * 128 + bi * 8 + w;
        int idx = b * 2048 + d * 32 + lane;
        float t1v = g_t1[idx];
        float v0 = eg0s[lane] * (1.f - t1v * t1v);
        float acc = 0.f;
        #pragma unroll
        for (int k = 0; k < 32; k++)
            acc = fmaf(eg1s[k * 32 + lane], __shfl_sync(WARP_FULL, v0, k), acc);
        float t2v = g_t2[idx];
        float term = eg2s[lane] * acc * (1.f - t2v * t2v);
        #pragma unroll
        for (int off = 16; off; off >>= 1) term += __shfl_xor_sync(WARP_FULL, term, off);

        if (lane == 0) {
            float g = logf(term);
            float outv = g_h2[b * 64 + d] + bias_d;
            float l;
            if (hasGate) {
                float z = g + gt;
                float sp1 = (z  > 20.f) ? z  : log1pf(expf(z));
                float sp0 = (gt > 20.f) ? gt : log1pf(expf(gt));
                l = sp1 - sp0;
                float sgm = 1.f / (1.f + expf(-gt));
                float xo = sgm * outv + (1.f - sgm) * xcur[b * 64 + d];
                xnext[b * 64 + (63 - d)] = xo;
                g_xf[b * 64 + (63 - d)] = __float2half(xo);
            } else {
                l = g;
                xnext[b * 64 + d] = outv;
            }
            if (accum) g_lterm[b * 64 + d] += l;
            else       g_lterm[b * 64 + d]  = l;
        }
    }
}

// ---------------- final reduction ----------------
__global__ void __launch_bounds__(256) final_kernel(int xsel, float* __restrict__ out) {
    const float* xf = (xsel == 1) ? (const float*)g_xA : (const float*)g_xB;
    int b = blockIdx.x * 8 + (threadIdx.x >> 5);
    int lane = threadIdx.x & 31;
    float v1 = xf[b * 64 + lane];
    float v2 = xf[b * 64 + 32 + lane];
    float s = -0.5f * (v1 * v1 + v2 * v2)
              + g_lterm[b * 64 + lane] + g_lterm[b * 64 + 32 + lane];
    #pragma unroll
    for (int off = 16; off; off >>= 1) s += __shfl_xor_sync(WARP_FULL, s, off);
    if (lane == 0) out[b] = s - 32.f * 1.8378770664093453f;
}

// ---------------- launch ----------------
extern "C" void kernel_launch(void* const* d_in, const int* in_sizes, int n_in,
                              void* d_out, int out_size) {
    (void)in_sizes; (void)n_in; (void)out_size;
    const float* x     = (const float*)d_in[0];
    const float* gate0 = (const float*)d_in[28];
    const float* gate1 = (const float*)d_in[29];

    PrepPtrs P;
    for (int f = 0; f < 3; f++)
        for (int l = 0; l < 3; l++) {
            P.W [f * 3 + l] = (const float*)d_in[1 + f * 9 + l * 3 + 0];
            P.dw[f * 3 + l] = (const float*)d_in[1 + f * 9 + l * 3 + 1];
        }
    prep_all_kernel<<<dim3(520, 3), 256>>>(P);
    xconv_kernel<<<256, 256>>>(x);

    int xsel = 0;
    for (int f = 0; f < 3; f++) {
        const float* b0 = (const float*)d_in[1 + f * 9 + 2];
        const float* b1 = (const float*)d_in[1 + f * 9 + 5];
        const float* b2 = (const float*)d_in[1 + f * 9 + 8];

        layer0h_kernel<<<dim3(32, 8), 256, L1_SMEM_BYTES>>>(f, b0);
        layer1_mma_kernel<<<dim3(32, 8, 8), 256, L1_SMEM_BYTES>>>(f);
        reduce1_kernel<<<dim3(32, 32), 256>>>(b1);
        layer2_mma_kernel<<<dim3(8, 16), 256, L1_SMEM_BYTES>>>(f);
        reduce2_kernel<<<64, 256>>>();

        const float* gate = (f == 0) ? gate0 : ((f == 1) ? gate1 : nullptr);
        int nsel = (f & 1) ? 2 : 1;
        jac_kernel<<<dim3(64, 8), 256>>>(x, xsel, nsel, f, gate, (f < 2) ? 1 : 0, (f > 0) ? 1 : 0, b2);
        xsel = nsel;
    }
    final_kernel<<<128, 256>>>(xsel, (float*)d_out);
}

// round 16
// speedup vs baseline: 1.2196x; 1.0480x over previous
#include <cuda_runtime.h>
#include <cuda_fp16.h>
#include <math.h>
#include <stdint.h>

#define WARP_FULL 0xFFFFFFFFu

// ---------------- scratch (device globals; no allocation) ----------------
__device__ __half g_wn0f[3][2048 * 64];     // [f][n][k] fp16 layer0 weights
__device__ __half g_wn1f[3][2048 * 2048];   // [f][n][k] fp16 layer1 weights
__device__ __half g_wn2f[3][64 * 2048];     // [f][n][k] fp16 layer2 weights
__device__ float  g_eg0 [3][2048];
__device__ float  g_eg1 [3][64 * 32 * 32];
__device__ float  g_eg2 [3][64 * 32];
__device__ __half g_xf [1024 * 64];         // fp16 flow input (GEMM path)
__device__ __half g_t1f [1024 * 2048];      // fp16 t1 (GEMM path)
__device__ __half g_tp1f[1024 * 2048];      // fp16 1-t1^2 (jac path)
__device__ __half g_t2f [1024 * 2048];      // fp16 t2 (GEMM path)
__device__ __half g_tp2f[1024 * 2048];      // fp16 1-t2^2 (jac path)
__device__ float  g_part[32 * 4 * 8 * 8192];  // K-split partials
__device__ float  g_h2 [1024 * 64];
__device__ float  g_xA [1024 * 64];
__device__ float  g_xB [1024 * 64];
__device__ float  g_lterm[1024 * 64];

struct PrepPtrs { const float* W[9]; const float* dw[9]; };

__device__ __forceinline__ void mma16816(float* c, const uint32_t* a, const uint32_t* b) {
    asm volatile("mma.sync.aligned.m16n8k16.row.col.f32.f16.f16.f32 "
        "{%0,%1,%2,%3}, {%4,%5,%6,%7}, {%8,%9}, {%0,%1,%2,%3};"
        : "+f"(c[0]), "+f"(c[1]), "+f"(c[2]), "+f"(c[3])
        : "r"(a[0]), "r"(a[1]), "r"(a[2]), "r"(a[3]), "r"(b[0]), "r"(b[1]));
}
__device__ __forceinline__ uint32_t smem_u32(const void* p) {
    uint32_t a;
    asm("{ .reg .u64 t; cvta.to.shared.u64 t, %1; cvt.u32.u64 %0, t; }" : "=r"(a) : "l"(p));
    return a;
}
__device__ __forceinline__ void cp16(uint32_t dst, const void* src) {
    asm volatile("cp.async.cg.shared.global [%0], [%1], 16;" :: "r"(dst), "l"(src));
}
#define CP_COMMIT() asm volatile("cp.async.commit_group;" ::: "memory")
#define CP_WAIT(n)  asm volatile("cp.async.wait_group %0;" :: "n"(n) : "memory")

// ---------------- merged weight preprocessing: warp per row ----------------
__global__ void __launch_bounds__(256) prep_all_kernel(PrepPtrs P) {
    int f = blockIdx.y;
    int wr = blockIdx.x * 8 + (threadIdx.x >> 5);
    int lane = threadIdx.x & 31;

    if (wr < 2048) {                        // ---- layer0 (fp16 [n][k])
        const float* W  = P.W [f * 3 + 0];
        const float* dw = P.dw[f * 3 + 0];
        int r = wr, blk = r >> 5;
        float vals[2]; float s = 0.f;
        #pragma unroll
        for (int i = 0; i < 2; i++) {
            int c = lane + 32 * i;
            float raw = W[r * 64 + c];
            float v = (c < blk) ? raw : ((c == blk) ? expf(raw) : 0.f);
            vals[i] = v; s += v * v;
        }
        #pragma unroll
        for (int off = 16; off; off >>= 1) s += __shfl_xor_sync(WARP_FULL, s, off);
        float scale = expf(dw[r]) * rsqrtf(s);
        #pragma unroll
        for (int i = 0; i < 2; i++) {
            int c = lane + 32 * i;
            float wv = vals[i] * scale;
            g_wn0f[f][r * 64 + c] = __float2half(wv);
            if (c == blk) g_eg0[f][r] = wv;
        }
    } else if (wr < 4096) {                 // ---- layer1 (fp16)
        const float* W  = P.W [f * 3 + 1];
        const float* dw = P.dw[f * 3 + 1];
        int r = wr - 2048, blk = r >> 5;
        int d0 = blk * 32, d1 = d0 + 32;
        int cmax = ((r >> 6) + 1) << 6;
        float s = 0.f;
        for (int c = lane; c < d1; c += 32) {
            float wv = W[r * 2048 + c];
            if (c >= d0) wv = expf(wv);
            s += wv * wv;
        }
        #pragma unroll
        for (int off = 16; off; off >>= 1) s += __shfl_xor_sync(WARP_FULL, s, off);
        float scale = expf(dw[r]) * rsqrtf(s);
        for (int c = lane; c < cmax; c += 32) {
            float o;
            if (c < d0)       o = W[r * 2048 + c] * scale;
            else if (c < d1) {
                o = expf(W[r * 2048 + c]) * scale;
                g_eg1[f][blk * 1024 + (c - d0) * 32 + (r & 31)] = o;
            } else            o = 0.f;
            g_wn1f[f][r * 2048 + c] = __float2half(o);
        }
    } else {                                // ---- layer2 (fp16 [n][k])
        const float* W  = P.W [f * 3 + 2];
        const float* dw = P.dw[f * 3 + 2];
        int r = wr - 4096;
        int d0 = r * 32, d1 = d0 + 32;
        float s = 0.f;
        for (int c = lane; c < d1; c += 32) {
            float wv = W[r * 2048 + c];
            if (c >= d0) wv = expf(wv);
            s += wv * wv;
        }
        #pragma unroll
        for (int off = 16; off; off >>= 1) s += __shfl_xor_sync(WARP_FULL, s, off);
        float scale = expf(dw[r]) * rsqrtf(s);
        for (int c = lane; c < 2048; c += 32) {
            float o;
            if (c < d0)       o = W[r * 2048 + c] * scale;
            else if (c < d1) {
                o = expf(W[r * 2048 + c]) * scale;
                g_eg2[f][r * 32 + (c - d0)] = o;
            } else            o = 0.f;
            g_wn2f[f][r * 2048 + c] = __float2half(o);
        }
    }
}

// ---------------- x conversion (flow 0 only) ----------------
__global__ void __launch_bounds__(256) xconv_kernel(const float* __restrict__ x) {
    int i = blockIdx.x * 256 + threadIdx.x;
    g_xf[i] = __float2half(x[i]);
}

// ---------------- shared HMMA core: 2-stage cp.async double buffer ----------------
#define L1_A 0
#define L1_B (128 * 40)
#define L1_BUF (192 * 40)                 // 7680 halves / buffer
#define L1_SMEM_BYTES (2 * L1_BUF * 2)    // 30720 bytes

__device__ __forceinline__ void hmma_core(const __half* __restrict__ Aglob, int m0, int astr,
                                          const __half* __restrict__ Bglob, int n0, int bstr,
                                          int kbeg, int kend, __half* smh,
                                          float acc[2][4][4]) {
    const uint32_t sb = smem_u32(smh);
    const int tid = threadIdx.x;
    const int w = tid >> 5, l = tid & 31;
    const int mw = (w & 3) * 32, nw = (w >> 2) * 32;
    const int lr = l >> 2, lc2 = (l & 3) * 2;
    const int ra = tid >> 2, qa = (tid & 3) * 8;

    auto load_chunk = [&](uint32_t base, int kc) {
        cp16(base + (uint32_t)(L1_A + ra * 40 + qa) * 2,        &Aglob[(m0 + ra) * astr + kc + qa]);
        cp16(base + (uint32_t)(L1_A + (ra + 64) * 40 + qa) * 2, &Aglob[(m0 + ra + 64) * astr + kc + qa]);
        cp16(base + (uint32_t)(L1_B + ra * 40 + qa) * 2,        &Bglob[(n0 + ra) * bstr + kc + qa]);
        CP_COMMIT();
    };

    load_chunk(sb, kbeg);
    int buf = 0;
    for (int kc = kbeg; kc < kend; kc += 32) {
        bool more = (kc + 32) < kend;
        if (more) load_chunk(sb + (uint32_t)(buf ^ 1) * L1_BUF * 2, kc + 32);
        if (more) { CP_WAIT(1); } else { CP_WAIT(0); }
        __syncthreads();

        const __half* S = smh + buf * L1_BUF;
        #pragma unroll
        for (int kk = 0; kk < 32; kk += 16) {
            uint32_t a[2][4], b[4][2];
            #pragma unroll
            for (int i = 0; i < 2; i++) {
                int R = mw + i * 16 + lr;
                a[i][0] = *(const uint32_t*)&S[L1_A + R * 40 + kk + lc2];
                a[i][1] = *(const uint32_t*)&S[L1_A + (R + 8) * 40 + kk + lc2];
                a[i][2] = *(const uint32_t*)&S[L1_A + R * 40 + kk + 8 + lc2];
                a[i][3] = *(const uint32_t*)&S[L1_A + (R + 8) * 40 + kk + 8 + lc2];
            }
            #pragma unroll
            for (int j = 0; j < 4; j++) {
                int N = nw + j * 8 + lr;
                b[j][0] = *(const uint32_t*)&S[L1_B + N * 40 + kk + lc2];
                b[j][1] = *(const uint32_t*)&S[L1_B + N * 40 + kk + 8 + lc2];
            }
            #pragma unroll
            for (int i = 0; i < 2; i++)
                #pragma unroll
                for (int j = 0; j < 4; j++)
                    mma16816(acc[i][j], a[i], b[j]);
        }
        __syncthreads();
        buf ^= 1;
    }
}

// ---------------- layer 0: t1 = tanh(xf @ wn0^T + b0) -> t1f + tp1f (fp16) ----------------
__global__ void __launch_bounds__(256) layer0h_kernel(int f, const float* __restrict__ bias) {
    extern __shared__ __half smh[];
    const int nt = blockIdx.x, mt = blockIdx.y;
    const int m0 = mt * 128, n0 = nt * 64;
    float acc[2][4][4] = {};
    hmma_core(g_xf, m0, 64, g_wn0f[f], n0, 64, 0, 64, smh, acc);

    const int tid = threadIdx.x;
    const int w = tid >> 5, l = tid & 31;
    const int mw = (w & 3) * 32, nw = (w >> 2) * 32;
    const int lr = l >> 2, lc2 = (l & 3) * 2;
    #pragma unroll
    for (int i = 0; i < 2; i++) {
        int r = m0 + mw + i * 16 + lr;
        #pragma unroll
        for (int j = 0; j < 4; j++) {
            int n = n0 + nw + j * 8 + lc2;
            float b0 = bias[n], b1 = bias[n + 1];
            float t0a = tanhf(acc[i][j][0] + b0);
            float t1a = tanhf(acc[i][j][1] + b1);
            float t0b = tanhf(acc[i][j][2] + b0);
            float t1b = tanhf(acc[i][j][3] + b1);
            *reinterpret_cast<__half2*>(&g_t1f [r * 2048 + n])       = __floats2half2_rn(t0a, t1a);
            *reinterpret_cast<__half2*>(&g_t1f [(r + 8) * 2048 + n]) = __floats2half2_rn(t0b, t1b);
            *reinterpret_cast<__half2*>(&g_tp1f[r * 2048 + n])       = __floats2half2_rn(1.f - t0a * t0a, 1.f - t1a * t1a);
            *reinterpret_cast<__half2*>(&g_tp1f[(r + 8) * 2048 + n]) = __floats2half2_rn(1.f - t0b * t0b, 1.f - t1b * t1b);
        }
    }
}

// ---------------- partial-writing epilogue (layers 1,2) ----------------
__device__ __forceinline__ void write_partials(float acc[2][4][4], float* __restrict__ out) {
    const int tid = threadIdx.x;
    const int w = tid >> 5, l = tid & 31;
    const int mw = (w & 3) * 32, nw = (w >> 2) * 32;
    const int lr = l >> 2, lc2 = (l & 3) * 2;
    #pragma unroll
    for (int i = 0; i < 2; i++) {
        int r = mw + i * 16 + lr;
        #pragma unroll
        for (int j = 0; j < 4; j++) {
            int n = nw + j * 8 + lc2;
            *reinterpret_cast<float2*>(&out[r * 64 + n])       = make_float2(acc[i][j][0], acc[i][j][1]);
            *reinterpret_cast<float2*>(&out[(r + 8) * 64 + n]) = make_float2(acc[i][j][2], acc[i][j][3]);
        }
    }
}

// ---------------- layer 1: fp16 HMMA, triangular K-split (512-wide chunks) ----------------
__global__ void __launch_bounds__(256) layer1_mma_kernel(int f) {
    const int nt = blockIdx.x, mt = blockIdx.y, ch = blockIdx.z;
    const int Klim = (nt + 1) * 64;
    const int kbeg = ch * 512;
    if (kbeg >= Klim) return;
    const int kend = min(kbeg + 512, Klim);
    extern __shared__ __half smh[];
    float acc[2][4][4] = {};
    hmma_core(g_t1f, mt * 128, 2048, g_wn1f[f], nt * 64, 2048, kbeg, kend, smh, acc);
    write_partials(acc, &g_part[(size_t)((nt * 4 + ch) * 8 + mt) * 8192]);
}

// ---------------- layer1 reduce: t2 = tanh(sum partials + b1) -> t2f + tp2f ----------------
__global__ void __launch_bounds__(256) reduce1_kernel(const float* __restrict__ bias) {
    const int nt = blockIdx.x, ms = blockIdx.y;
    const int mt = ms >> 2, sub = ms & 3;
    const int Cnt = (nt + 8) >> 3;
    const int n0 = nt * 64;
    const float* base = &g_part[(size_t)((nt * 4) * 8 + mt) * 8192 + sub * 2048];
    const int row0 = mt * 128 + sub * 32;
    for (int e = threadIdx.x * 4; e < 2048; e += 1024) {
        float4 s = *reinterpret_cast<const float4*>(&base[e]);
        for (int c = 1; c < Cnt; c++) {
            float4 p = *reinterpret_cast<const float4*>(&base[(size_t)c * 65536 + e]);
            s.x += p.x; s.y += p.y; s.z += p.z; s.w += p.w;
        }
        int m = e >> 6, n = e & 63;
        float4 bv = *reinterpret_cast<const float4*>(&bias[n0 + n]);
        float4 o;
        o.x = tanhf(s.x + bv.x); o.y = tanhf(s.y + bv.y);
        o.z = tanhf(s.z + bv.z); o.w = tanhf(s.w + bv.w);
        int idx = (row0 + m) * 2048 + n0 + n;
        *reinterpret_cast<__half2*>(&g_t2f[idx])      = __floats2half2_rn(o.x, o.y);
        *reinterpret_cast<__half2*>(&g_t2f[idx + 2])  = __floats2half2_rn(o.z, o.w);
        *reinterpret_cast<__half2*>(&g_tp2f[idx])     = __floats2half2_rn(1.f - o.x * o.x, 1.f - o.y * o.y);
        *reinterpret_cast<__half2*>(&g_tp2f[idx + 2]) = __floats2half2_rn(1.f - o.z * o.z, 1.f - o.w * o.w);
    }
}

// ---------------- layer 2: fp16 HMMA, K-split 16 x 128 ----------------
__global__ void __launch_bounds__(256) layer2_mma_kernel(int f) {
    const int mt = blockIdx.x, ch = blockIdx.y;
    extern __shared__ __half smh[];
    float acc[2][4][4] = {};
    hmma_core(g_t2f, mt * 128, 2048, g_wn2f[f], 0, 2048, ch * 128, ch * 128 + 128, smh, acc);
    write_partials(acc, &g_part[(size_t)(ch * 8 + mt) * 8192]);
}

// ---------------- layer2 reduce: h2 = sum partials ----------------
__global__ void __launch_bounds__(256) reduce2_kernel() {
    int gidx = blockIdx.x * 1024 + threadIdx.x * 4;     // 0..65535
    float4 s = *reinterpret_cast<const float4*>(&g_part[gidx]);
    #pragma unroll
    for (int c = 1; c < 16; c++) {
        float4 p = *reinterpret_cast<const float4*>(&g_part[(size_t)c * 65536 + gidx]);
        s.x += p.x; s.y += p.y; s.z += p.z; s.w += p.w;
    }
    int m = (gidx >> 13) * 128 + ((gidx & 8191) >> 6);
    int n = gidx & 63;
    *reinterpret_cast<float4*>(&g_h2[m * 64 + n]) = s;
}

// ---------------- Jacobian chain + gate + flip (fp16 tp planes) ----------------
__global__ void __launch_bounds__(256) jac_kernel(const float* __restrict__ xext,
                                                  int xsel, int nsel, int f,
                                                  const float* __restrict__ gate,
                                                  int hasGate, int accum,
                                                  const float* __restrict__ b2) {
    __shared__ float eg1s[1024];
    __shared__ float eg0s[32];
    __shared__ float eg2s[32];
    int d = blockIdx.x;
    int lane = threadIdx.x & 31, w = threadIdx.x >> 5;
    for (int i = threadIdx.x; i < 1024; i += 256) eg1s[i] = g_eg1[f][d * 1024 + i];
    if (threadIdx.x < 32) {
        eg0s[threadIdx.x] = g_eg0[f][d * 32 + threadIdx.x];
        eg2s[threadIdx.x] = g_eg2[f][d * 32 + threadIdx.x];
    }
    __syncthreads();
    const float* xcur = (xsel == 0) ? xext : ((xsel == 1) ? (const float*)g_xA : (const float*)g_xB);
    float* xnext = (nsel == 1) ? g_xA : g_xB;
    float gt = 0.f;
    if (hasGate) gt = *gate;
    float bias_d = b2[d];

    for (int bi = 0; bi < 16; bi++) {
        int b = blockIdx.y * 128 + bi * 8 + w;
        int idx = b * 2048 + d * 32 + lane;
        float v0 = eg0s[lane] * __half2float(g_tp1f[idx]);
        float acc = 0.f;
        #pragma unroll
        for (int k = 0; k < 32; k++)
            acc = fmaf(eg1s[k * 32 + lane], __shfl_sync(WARP_FULL, v0, k), acc);
        float term = eg2s[lane] * acc * __half2float(g_tp2f[idx]);
        #pragma unroll
        for (int off = 16; off; off >>= 1) term += __shfl_xor_sync(WARP_FULL, term, off);

        if (lane == 0) {
            float g = logf(term);
            float outv = g_h2[b * 64 + d] + bias_d;
            float l;
            if (hasGate) {
                float z = g + gt;
                float sp1 = (z  > 20.f) ? z  : log1pf(expf(z));
                float sp0 = (gt > 20.f) ? gt : log1pf(expf(gt));
                l = sp1 - sp0;
                float sgm = 1.f / (1.f + expf(-gt));
                float xo = sgm * outv + (1.f - sgm) * xcur[b * 64 + d];
                xnext[b * 64 + (63 - d)] = xo;
                g_xf[b * 64 + (63 - d)] = __float2half(xo);
            } else {
                l = g;
                xnext[b * 64 + d] = outv;
            }
            if (accum) g_lterm[b * 64 + d] += l;
            else       g_lterm[b * 64 + d]  = l;
        }
    }
}

// ---------------- final reduction ----------------
__global__ void __launch_bounds__(256) final_kernel(int xsel, float* __restrict__ out) {
    const float* xf = (xsel == 1) ? (const float*)g_xA : (const float*)g_xB;
    int b = blockIdx.x * 8 + (threadIdx.x >> 5);
    int lane = threadIdx.x & 31;
    float v1 = xf[b * 64 + lane];
    float v2 = xf[b * 64 + 32 + lane];
    float s = -0.5f * (v1 * v1 + v2 * v2)
              + g_lterm[b * 64 + lane] + g_lterm[b * 64 + 32 + lane];
    #pragma unroll
    for (int off = 16; off; off >>= 1) s += __shfl_xor_sync(WARP_FULL, s, off);
    if (lane == 0) out[b] = s - 32.f * 1.8378770664093453f;
}

// ---------------- launch ----------------
extern "C" void kernel_launch(void* const* d_in, const int* in_sizes, int n_in,
                              void* d_out, int out_size) {
    (void)in_sizes; (void)n_in; (void)out_size;
    const float* x     = (const float*)d_in[0];
    const float* gate0 = (const float*)d_in[28];
    const float* gate1 = (const float*)d_in[29];

    PrepPtrs P;
    for (int f = 0; f < 3; f++)
        for (int l = 0; l < 3; l++) {
            P.W [f * 3 + l] = (const float*)d_in[1 + f * 9 + l * 3 + 0];
            P.dw[f * 3 + l] = (const float*)d_in[1 + f * 9 + l * 3 + 1];
        }
    prep_all_kernel<<<dim3(520, 3), 256>>>(P);
    xconv_kernel<<<256, 256>>>(x);

    int xsel = 0;
    for (int f = 0; f < 3; f++) {
        const float* b0 = (const float*)d_in[1 + f * 9 + 2];
        const float* b1 = (const float*)d_in[1 + f * 9 + 5];
        const float* b2 = (const float*)d_in[1 + f * 9 + 8];

        layer0h_kernel<<<dim3(32, 8), 256, L1_SMEM_BYTES>>>(f, b0);
        layer1_mma_kernel<<<dim3(32, 8, 4), 256, L1_SMEM_BYTES>>>(f);
        reduce1_kernel<<<dim3(32, 32), 256>>>(b1);
        layer2_mma_kernel<<<dim3(8, 16), 256, L1_SMEM_BYTES>>>(f);
        reduce2_kernel<<<64, 256>>>();

        const float* gate = (f == 0) ? gate0 : ((f == 1) ? gate1 : nullptr);
        int nsel = (f & 1) ? 2 : 1;
        jac_kernel<<<dim3(64, 8), 256>>>(x, xsel, nsel, f, gate, (f < 2) ? 1 : 0, (f > 0) ? 1 : 0, b2);
        xsel = nsel;
    }
    final_kernel<<<128, 256>>>(xsel, (float*)d_out);
}

// round 17
// speedup vs baseline: 1.3837x; 1.1346x over previous
#include <cuda_runtime.h>
#include <cuda_fp16.h>
#include <math.h>
#include <stdint.h>

#define WARP_FULL 0xFFFFFFFFu

// ---------------- scratch (device globals; no allocation) ----------------
__device__ __half g_wn0f[3][2048 * 64];     // [f][n][k] fp16 layer0 weights
__device__ __half g_wn1f[3][2048 * 2048];   // [f][n][k] fp16 layer1 weights
__device__ __half g_wn2f[3][64 * 2048];     // [f][n][k] fp16 layer2 weights
__device__ float  g_eg0 [3][2048];
__device__ float  g_eg1 [3][64 * 32 * 32];
__device__ float  g_eg2 [3][64 * 32];
__device__ __half g_xf [1024 * 64];         // fp16 flow input (GEMM path)
__device__ __half g_t1f [1024 * 2048];      // fp16 t1 (GEMM path)
__device__ __half g_tp1f[1024 * 2048];      // fp16 1-t1^2 (jac path)
__device__ __half g_t2f [1024 * 2048];      // fp16 t2 (GEMM path)
__device__ __half g_tp2f[1024 * 2048];      // fp16 1-t2^2 (jac path)
__device__ float  g_part[32 * 4 * 8 * 8192];  // K-split partials (layer1 & layer2 reuse)
__device__ float  g_xA [1024 * 64];
__device__ float  g_xB [1024 * 64];
__device__ float  g_lterm[1024 * 64];

struct PrepPtrs { const float* W[9]; const float* dw[9]; };

__device__ __forceinline__ void mma16816(float* c, const uint32_t* a, const uint32_t* b) {
    asm volatile("mma.sync.aligned.m16n8k16.row.col.f32.f16.f16.f32 "
        "{%0,%1,%2,%3}, {%4,%5,%6,%7}, {%8,%9}, {%0,%1,%2,%3};"
        : "+f"(c[0]), "+f"(c[1]), "+f"(c[2]), "+f"(c[3])
        : "r"(a[0]), "r"(a[1]), "r"(a[2]), "r"(a[3]), "r"(b[0]), "r"(b[1]));
}
__device__ __forceinline__ uint32_t smem_u32(const void* p) {
    uint32_t a;
    asm("{ .reg .u64 t; cvta.to.shared.u64 t, %1; cvt.u32.u64 %0, t; }" : "=r"(a) : "l"(p));
    return a;
}
__device__ __forceinline__ void cp16(uint32_t dst, const void* src) {
    asm volatile("cp.async.cg.shared.global [%0], [%1], 16;" :: "r"(dst), "l"(src));
}
#define CP_COMMIT() asm volatile("cp.async.commit_group;" ::: "memory")
#define CP_WAIT(n)  asm volatile("cp.async.wait_group %0;" :: "n"(n) : "memory")

// ---------------- merged weight preprocessing: warp per row ----------------
__global__ void __launch_bounds__(256) prep_all_kernel(PrepPtrs P) {
    int f = blockIdx.y;
    int wr = blockIdx.x * 8 + (threadIdx.x >> 5);
    int lane = threadIdx.x & 31;

    if (wr < 2048) {                        // ---- layer0 (fp16 [n][k])
        const float* W  = P.W [f * 3 + 0];
        const float* dw = P.dw[f * 3 + 0];
        int r = wr, blk = r >> 5;
        float vals[2]; float s = 0.f;
        #pragma unroll
        for (int i = 0; i < 2; i++) {
            int c = lane + 32 * i;
            float raw = W[r * 64 + c];
            float v = (c < blk) ? raw : ((c == blk) ? expf(raw) : 0.f);
            vals[i] = v; s += v * v;
        }
        #pragma unroll
        for (int off = 16; off; off >>= 1) s += __shfl_xor_sync(WARP_FULL, s, off);
        float scale = expf(dw[r]) * rsqrtf(s);
        #pragma unroll
        for (int i = 0; i < 2; i++) {
            int c = lane + 32 * i;
            float wv = vals[i] * scale;
            g_wn0f[f][r * 64 + c] = __float2half(wv);
            if (c == blk) g_eg0[f][r] = wv;
        }
    } else if (wr < 4096) {                 // ---- layer1 (fp16)
        const float* W  = P.W [f * 3 + 1];
        const float* dw = P.dw[f * 3 + 1];
        int r = wr - 2048, blk = r >> 5;
        int d0 = blk * 32, d1 = d0 + 32;
        int cmax = ((r >> 6) + 1) << 6;
        float s = 0.f;
        for (int c = lane; c < d1; c += 32) {
            float wv = W[r * 2048 + c];
            if (c >= d0) wv = expf(wv);
            s += wv * wv;
        }
        #pragma unroll
        for (int off = 16; off; off >>= 1) s += __shfl_xor_sync(WARP_FULL, s, off);
        float scale = expf(dw[r]) * rsqrtf(s);
        for (int c = lane; c < cmax; c += 32) {
            float o;
            if (c < d0)       o = W[r * 2048 + c] * scale;
            else if (c < d1) {
                o = expf(W[r * 2048 + c]) * scale;
                g_eg1[f][blk * 1024 + (c - d0) * 32 + (r & 31)] = o;
            } else            o = 0.f;
            g_wn1f[f][r * 2048 + c] = __float2half(o);
        }
    } else {                                // ---- layer2 (fp16 [n][k])
        const float* W  = P.W [f * 3 + 2];
        const float* dw = P.dw[f * 3 + 2];
        int r = wr - 4096;
        int d0 = r * 32, d1 = d0 + 32;
        float s = 0.f;
        for (int c = lane; c < d1; c += 32) {
            float wv = W[r * 2048 + c];
            if (c >= d0) wv = expf(wv);
            s += wv * wv;
        }
        #pragma unroll
        for (int off = 16; off; off >>= 1) s += __shfl_xor_sync(WARP_FULL, s, off);
        float scale = expf(dw[r]) * rsqrtf(s);
        for (int c = lane; c < 2048; c += 32) {
            float o;
            if (c < d0)       o = W[r * 2048 + c] * scale;
            else if (c < d1) {
                o = expf(W[r * 2048 + c]) * scale;
                g_eg2[f][r * 32 + (c - d0)] = o;
            } else            o = 0.f;
            g_wn2f[f][r * 2048 + c] = __float2half(o);
        }
    }
}

// ---------------- x conversion (flow 0 only) ----------------
__global__ void __launch_bounds__(256) xconv_kernel(const float* __restrict__ x) {
    int i = blockIdx.x * 256 + threadIdx.x;
    g_xf[i] = __float2half(x[i]);
}

// ---------------- shared HMMA core: 2-stage cp.async double buffer ----------------
#define L1_A 0
#define L1_B (128 * 40)
#define L1_BUF (192 * 40)                 // 7680 halves / buffer
#define L1_SMEM_BYTES (2 * L1_BUF * 2)    // 30720 bytes

__device__ __forceinline__ void hmma_core(const __half* __restrict__ Aglob, int m0, int astr,
                                          const __half* __restrict__ Bglob, int n0, int bstr,
                                          int kbeg, int kend, __half* smh,
                                          float acc[2][4][4]) {
    const uint32_t sb = smem_u32(smh);
    const int tid = threadIdx.x;
    const int w = tid >> 5, l = tid & 31;
    const int mw = (w & 3) * 32, nw = (w >> 2) * 32;
    const int lr = l >> 2, lc2 = (l & 3) * 2;
    const int ra = tid >> 2, qa = (tid & 3) * 8;

    auto load_chunk = [&](uint32_t base, int kc) {
        cp16(base + (uint32_t)(L1_A + ra * 40 + qa) * 2,        &Aglob[(m0 + ra) * astr + kc + qa]);
        cp16(base + (uint32_t)(L1_A + (ra + 64) * 40 + qa) * 2, &Aglob[(m0 + ra + 64) * astr + kc + qa]);
        cp16(base + (uint32_t)(L1_B + ra * 40 + qa) * 2,        &Bglob[(n0 + ra) * bstr + kc + qa]);
        CP_COMMIT();
    };

    load_chunk(sb, kbeg);
    int buf = 0;
    for (int kc = kbeg; kc < kend; kc += 32) {
        bool more = (kc + 32) < kend;
        if (more) load_chunk(sb + (uint32_t)(buf ^ 1) * L1_BUF * 2, kc + 32);
        if (more) { CP_WAIT(1); } else { CP_WAIT(0); }
        __syncthreads();

        const __half* S = smh + buf * L1_BUF;
        #pragma unroll
        for (int kk = 0; kk < 32; kk += 16) {
            uint32_t a[2][4], b[4][2];
            #pragma unroll
            for (int i = 0; i < 2; i++) {
                int R = mw + i * 16 + lr;
                a[i][0] = *(const uint32_t*)&S[L1_A + R * 40 + kk + lc2];
                a[i][1] = *(const uint32_t*)&S[L1_A + (R + 8) * 40 + kk + lc2];
                a[i][2] = *(const uint32_t*)&S[L1_A + R * 40 + kk + 8 + lc2];
                a[i][3] = *(const uint32_t*)&S[L1_A + (R + 8) * 40 + kk + 8 + lc2];
            }
            #pragma unroll
            for (int j = 0; j < 4; j++) {
                int N = nw + j * 8 + lr;
                b[j][0] = *(const uint32_t*)&S[L1_B + N * 40 + kk + lc2];
                b[j][1] = *(const uint32_t*)&S[L1_B + N * 40 + kk + 8 + lc2];
            }
            #pragma unroll
            for (int i = 0; i < 2; i++)
                #pragma unroll
                for (int j = 0; j < 4; j++)
                    mma16816(acc[i][j], a[i], b[j]);
        }
        __syncthreads();
        buf ^= 1;
    }
}

// ---------------- layer 0: t1 = tanh(xf @ wn0^T + b0) -> t1f + tp1f (fp16) ----------------
__global__ void __launch_bounds__(256) layer0h_kernel(int f, const float* __restrict__ bias) {
    extern __shared__ __half smh[];
    const int nt = blockIdx.x, mt = blockIdx.y;
    const int m0 = mt * 128, n0 = nt * 64;
    float acc[2][4][4] = {};
    hmma_core(g_xf, m0, 64, g_wn0f[f], n0, 64, 0, 64, smh, acc);

    const int tid = threadIdx.x;
    const int w = tid >> 5, l = tid & 31;
    const int mw = (w & 3) * 32, nw = (w >> 2) * 32;
    const int lr = l >> 2, lc2 = (l & 3) * 2;
    #pragma unroll
    for (int i = 0; i < 2; i++) {
        int r = m0 + mw + i * 16 + lr;
        #pragma unroll
        for (int j = 0; j < 4; j++) {
            int n = n0 + nw + j * 8 + lc2;
            float b0 = bias[n], b1 = bias[n + 1];
            float t0a = tanhf(acc[i][j][0] + b0);
            float t1a = tanhf(acc[i][j][1] + b1);
            float t0b = tanhf(acc[i][j][2] + b0);
            float t1b = tanhf(acc[i][j][3] + b1);
            *reinterpret_cast<__half2*>(&g_t1f [r * 2048 + n])       = __floats2half2_rn(t0a, t1a);
            *reinterpret_cast<__half2*>(&g_t1f [(r + 8) * 2048 + n]) = __floats2half2_rn(t0b, t1b);
            *reinterpret_cast<__half2*>(&g_tp1f[r * 2048 + n])       = __floats2half2_rn(1.f - t0a * t0a, 1.f - t1a * t1a);
            *reinterpret_cast<__half2*>(&g_tp1f[(r + 8) * 2048 + n]) = __floats2half2_rn(1.f - t0b * t0b, 1.f - t1b * t1b);
        }
    }
}

// ---------------- partial-writing epilogue (layers 1,2) ----------------
__device__ __forceinline__ void write_partials(float acc[2][4][4], float* __restrict__ out) {
    const int tid = threadIdx.x;
    const int w = tid >> 5, l = tid & 31;
    const int mw = (w & 3) * 32, nw = (w >> 2) * 32;
    const int lr = l >> 2, lc2 = (l & 3) * 2;
    #pragma unroll
    for (int i = 0; i < 2; i++) {
        int r = mw + i * 16 + lr;
        #pragma unroll
        for (int j = 0; j < 4; j++) {
            int n = nw + j * 8 + lc2;
            *reinterpret_cast<float2*>(&out[r * 64 + n])       = make_float2(acc[i][j][0], acc[i][j][1]);
            *reinterpret_cast<float2*>(&out[(r + 8) * 64 + n]) = make_float2(acc[i][j][2], acc[i][j][3]);
        }
    }
}

// ---------------- layer 1: fp16 HMMA, triangular K-split (512-wide chunks) ----------------
__global__ void __launch_bounds__(256) layer1_mma_kernel(int f) {
    const int nt = blockIdx.x, mt = blockIdx.y, ch = blockIdx.z;
    const int Klim = (nt + 1) * 64;
    const int kbeg = ch * 512;
    if (kbeg >= Klim) return;
    const int kend = min(kbeg + 512, Klim);
    extern __shared__ __half smh[];
    float acc[2][4][4] = {};
    hmma_core(g_t1f, mt * 128, 2048, g_wn1f[f], nt * 64, 2048, kbeg, kend, smh, acc);
    write_partials(acc, &g_part[(size_t)((nt * 4 + ch) * 8 + mt) * 8192]);
}

// ---------------- layer1 reduce: t2 = tanh(sum partials + b1) -> t2f + tp2f ----------------
__global__ void __launch_bounds__(256) reduce1_kernel(const float* __restrict__ bias) {
    const int nt = blockIdx.x, ms = blockIdx.y;
    const int mt = ms >> 2, sub = ms & 3;
    const int Cnt = (nt + 8) >> 3;
    const int n0 = nt * 64;
    const float* base = &g_part[(size_t)((nt * 4) * 8 + mt) * 8192 + sub * 2048];
    const int row0 = mt * 128 + sub * 32;
    for (int e = threadIdx.x * 4; e < 2048; e += 1024) {
        float4 s = *reinterpret_cast<const float4*>(&base[e]);
        for (int c = 1; c < Cnt; c++) {
            float4 p = *reinterpret_cast<const float4*>(&base[(size_t)c * 65536 + e]);
            s.x += p.x; s.y += p.y; s.z += p.z; s.w += p.w;
        }
        int m = e >> 6, n = e & 63;
        float4 bv = *reinterpret_cast<const float4*>(&bias[n0 + n]);
        float4 o;
        o.x = tanhf(s.x + bv.x); o.y = tanhf(s.y + bv.y);
        o.z = tanhf(s.z + bv.z); o.w = tanhf(s.w + bv.w);
        int idx = (row0 + m) * 2048 + n0 + n;
        *reinterpret_cast<__half2*>(&g_t2f[idx])      = __floats2half2_rn(o.x, o.y);
        *reinterpret_cast<__half2*>(&g_t2f[idx + 2])  = __floats2half2_rn(o.z, o.w);
        *reinterpret_cast<__half2*>(&g_tp2f[idx])     = __floats2half2_rn(1.f - o.x * o.x, 1.f - o.y * o.y);
        *reinterpret_cast<__half2*>(&g_tp2f[idx + 2]) = __floats2half2_rn(1.f - o.z * o.z, 1.f - o.w * o.w);
    }
}

// ---------------- layer 2: fp16 HMMA, K-split 16 x 128 (partials summed in jac) ----------------
__global__ void __launch_bounds__(256) layer2_mma_kernel(int f) {
    const int mt = blockIdx.x, ch = blockIdx.y;
    extern __shared__ __half smh[];
    float acc[2][4][4] = {};
    hmma_core(g_t2f, mt * 128, 2048, g_wn2f[f], 0, 2048, ch * 128, ch * 128 + 128, smh, acc);
    write_partials(acc, &g_part[(size_t)(ch * 8 + mt) * 8192]);
}

// ---------------- Jacobian chain + gate + flip + layer2 partial-sum ----------------
// grid (64 d, 8 bslice), 256 threads. Warp w handles 16 b's in 4 groups of 4.
__global__ void __launch_bounds__(256) jac_kernel(const float* __restrict__ xext,
                                                  int xsel, int nsel, int f,
                                                  const float* __restrict__ gate,
                                                  int hasGate, int accum,
                                                  const float* __restrict__ b2) {
    __shared__ float eg1s[1024];
    __shared__ float eg0s[32];
    __shared__ float eg2s[32];
    __shared__ float v0s[8][4][32];
    int d = blockIdx.x;
    int lane = threadIdx.x & 31, w = threadIdx.x >> 5;
    for (int i = threadIdx.x; i < 1024; i += 256) eg1s[i] = g_eg1[f][d * 1024 + i];
    if (threadIdx.x < 32) {
        eg0s[threadIdx.x] = g_eg0[f][d * 32 + threadIdx.x];
        eg2s[threadIdx.x] = g_eg2[f][d * 32 + threadIdx.x];
    }
    __syncthreads();
    const float* xcur = (xsel == 0) ? xext : ((xsel == 1) ? (const float*)g_xA : (const float*)g_xB);
    float* xnext = (nsel == 1) ? g_xA : g_xB;
    float gt = 0.f, sgm = 0.f, sp0 = 0.f;
    if (hasGate) {
        gt = *gate;
        sgm = 1.f / (1.f + expf(-gt));
        sp0 = (gt > 20.f) ? gt : log1pf(expf(gt));
    }
    float bias_d = b2[d];

    for (int g4 = 0; g4 < 4; g4++) {
        int b0 = blockIdx.y * 128 + w * 16 + g4 * 4;
        // stage v0 for 4 batch rows
        #pragma unroll
        for (int j = 0; j < 4; j++) {
            int idx = (b0 + j) * 2048 + d * 32 + lane;
            v0s[w][j][lane] = eg0s[lane] * __half2float(g_tp1f[idx]);
        }
        __syncwarp();
        float acc[4] = {};
        #pragma unroll 4
        for (int k = 0; k < 32; k++) {
            float e = eg1s[k * 32 + lane];
            acc[0] = fmaf(e, v0s[w][0][k], acc[0]);
            acc[1] = fmaf(e, v0s[w][1][k], acc[1]);
            acc[2] = fmaf(e, v0s[w][2][k], acc[2]);
            acc[3] = fmaf(e, v0s[w][3][k], acc[3]);
        }
        float term[4];
        #pragma unroll
        for (int j = 0; j < 4; j++) {
            int idx = (b0 + j) * 2048 + d * 32 + lane;
            term[j] = eg2s[lane] * acc[j] * __half2float(g_tp2f[idx]);
        }
        // interleaved butterflies (4 independent chains)
        #pragma unroll
        for (int off = 16; off; off >>= 1) {
            #pragma unroll
            for (int j = 0; j < 4; j++)
                term[j] += __shfl_xor_sync(WARP_FULL, term[j], off);
        }
        if (lane < 4) {
            int j = lane;
            int b = b0 + j;
            float gv = logf(term[j]);
            // layer2 output: sum 16 K-chunk partials + bias
            int mt = b >> 7, lm = b & 127;
            float h = bias_d;
            #pragma unroll
            for (int c = 0; c < 16; c++)
                h += g_part[(size_t)(c * 8 + mt) * 8192 + lm * 64 + d];
            float l;
            if (hasGate) {
                float z = gv + gt;
                float sp1 = (z > 20.f) ? z : log1pf(expf(z));
                l = sp1 - sp0;
                float xo = sgm * h + (1.f - sgm) * xcur[b * 64 + d];
                xnext[b * 64 + (63 - d)] = xo;
                g_xf[b * 64 + (63 - d)] = __float2half(xo);
            } else {
                l = gv;
                xnext[b * 64 + d] = h;
            }
            if (accum) g_lterm[b * 64 + d] += l;
            else       g_lterm[b * 64 + d]  = l;
        }
        __syncwarp();
    }
}

// ---------------- final reduction ----------------
__global__ void __launch_bounds__(256) final_kernel(int xsel, float* __restrict__ out) {
    const float* xf = (xsel == 1) ? (const float*)g_xA : (const float*)g_xB;
    int b = blockIdx.x * 8 + (threadIdx.x >> 5);
    int lane = threadIdx.x & 31;
    float v1 = xf[b * 64 + lane];
    float v2 = xf[b * 64 + 32 + lane];
    float s = -0.5f * (v1 * v1 + v2 * v2)
              + g_lterm[b * 64 + lane] + g_lterm[b * 64 + 32 + lane];
    #pragma unroll
    for (int off = 16; off; off >>= 1) s += __shfl_xor_sync(WARP_FULL, s, off);
    if (lane == 0) out[b] = s - 32.f * 1.8378770664093453f;
}

// ---------------- launch ----------------
extern "C" void kernel_launch(void* const* d_in, const int* in_sizes, int n_in,
                              void* d_out, int out_size) {
    (void)in_sizes; (void)n_in; (void)out_size;
    const float* x     = (const float*)d_in[0];
    const float* gate0 = (const float*)d_in[28];
    const float* gate1 = (const float*)d_in[29];

    PrepPtrs P;
    for (int f = 0; f < 3; f++)
        for (int l = 0; l < 3; l++) {
            P.W [f * 3 + l] = (const float*)d_in[1 + f * 9 + l * 3 + 0];
            P.dw[f * 3 + l] = (const float*)d_in[1 + f * 9 + l * 3 + 1];
        }
    prep_all_kernel<<<dim3(520, 3), 256>>>(P);
    xconv_kernel<<<256, 256>>>(x);

    int xsel = 0;
    for (int f = 0; f < 3; f++) {
        const float* b0 = (const float*)d_in[1 + f * 9 + 2];
        const float* b1 = (const float*)d_in[1 + f * 9 + 5];
        const float* b2 = (const float*)d_in[1 + f * 9 + 8];

        layer0h_kernel<<<dim3(32, 8), 256, L1_SMEM_BYTES>>>(f, b0);
        layer1_mma_kernel<<<dim3(32, 8, 4), 256, L1_SMEM_BYTES>>>(f);
        reduce1_kernel<<<dim3(32, 32), 256>>>(b1);
        layer2_mma_kernel<<<dim3(8, 16), 256, L1_SMEM_BYTES>>>(f);

        const float* gate = (f == 0) ? gate0 : ((f == 1) ? gate1 : nullptr);
        int nsel = (f & 1) ? 2 : 1;
        jac_kernel<<<dim3(64, 8), 256>>>(x, xsel, nsel, f, gate, (f < 2) ? 1 : 0, (f > 0) ? 1 : 0, b2);
        xsel = nsel;
    }
    final_kernel<<<128, 256>>>(xsel, (float*)d_out);
}